// round 14
// baseline (speedup 1.0000x reference)
#include <cuda_runtime.h>
#include <cuda_fp16.h>
#include <stdint.h>

// Problem dims
#define B_  2
#define S_  2048
#define D_  1024
#define H_  16
#define HD_ 64
#define BS_ (B_ * S_)         // 4096
#define NX  (BS_ * D_)
#define NW  (H_ * D_ * HD_)
#define LOG2E 1.4426950408889634f

// fp16 scratch (device globals — allocation-guard safe)
__device__ __align__(16) __half g_xh[NX];
__device__ __align__(16) __half g_wT[3 * D_ * D_];   // [mat][n=h*64+e][k]
__device__ __align__(16) __half g_woh[D_ * D_];      // [n][k]
__device__ float g_bqs[H_ * HD_];                    // bq * 0.125 * log2e
__device__ __align__(16) __half g_q[B_ * H_ * S_ * HD_];   // pre-scaled
__device__ __align__(16) __half g_k[B_ * H_ * S_ * HD_];
__device__ __align__(16) __half g_v[B_ * H_ * S_ * HD_];
__device__ __align__(16) __half g_wv[BS_ * D_];            // [B,S,H*HD]

__device__ __forceinline__ uint32_t smem_u32(const void* p) {
    uint32_t a;
    asm("{ .reg .u64 t; cvta.to.shared.u64 t, %1; cvt.u32.u64 %0, t; }"
        : "=r"(a) : "l"(p));
    return a;
}

__device__ __forceinline__ void mma_f16(float c[4], const uint32_t a[4],
                                        uint32_t b0, uint32_t b1) {
    asm volatile(
        "mma.sync.aligned.m16n8k16.row.col.f32.f16.f16.f32 "
        "{%0,%1,%2,%3}, {%4,%5,%6,%7}, {%8,%9}, {%0,%1,%2,%3};"
        : "+f"(c[0]), "+f"(c[1]), "+f"(c[2]), "+f"(c[3])
        : "r"(a[0]), "r"(a[1]), "r"(a[2]), "r"(a[3]), "r"(b0), "r"(b1));
}
__device__ __forceinline__ void ldm4(uint32_t r[4], uint32_t addr) {
    asm volatile("ldmatrix.sync.aligned.m8n8.x4.shared.b16 {%0,%1,%2,%3}, [%4];"
        : "=r"(r[0]), "=r"(r[1]), "=r"(r[2]), "=r"(r[3]) : "r"(addr));
}
__device__ __forceinline__ void ldm4t(uint32_t r[4], uint32_t addr) {
    asm volatile("ldmatrix.sync.aligned.m8n8.x4.trans.shared.b16 {%0,%1,%2,%3}, [%4];"
        : "=r"(r[0]), "=r"(r[1]), "=r"(r[2]), "=r"(r[3]) : "r"(addr));
}

#define CP16(d, s)  asm volatile("cp.async.cg.shared.global [%0], [%1], 16;" :: "r"(d), "l"(s))
#define CPCOMMIT()  asm volatile("cp.async.commit_group;")
#define CPWAIT(n)   asm volatile("cp.async.wait_group %0;" :: "n"(n))

// ---------------------------------------------------------------------------
// Convert (vectorized): x -> fp16, Wo -> fp16 [n][k], bq scaled
// ---------------------------------------------------------------------------
#define NX4 (NX / 4)
#define ND4 (D_ * D_ / 4)
__global__ __launch_bounds__(256) void convert_kernel(
    const float* __restrict__ x, const float* __restrict__ bq,
    const float* __restrict__ Wo)
{
    long long i = (long long)blockIdx.x * 256 + threadIdx.x;
    if (i < NX4) {
        float4 v = ((const float4*)x)[i];
        __half2 h0 = __floats2half2_rn(v.x, v.y);
        __half2 h1 = __floats2half2_rn(v.z, v.w);
        ((uint2*)g_xh)[i] = make_uint2(*(uint32_t*)&h0, *(uint32_t*)&h1);
        return;
    }
    i -= NX4;
    if (i < ND4) {
        float4 v = ((const float4*)Wo)[i];
        __half2 h0 = __floats2half2_rn(v.x, v.y);
        __half2 h1 = __floats2half2_rn(v.z, v.w);
        ((uint2*)g_woh)[i] = make_uint2(*(uint32_t*)&h0, *(uint32_t*)&h1);
        return;
    }
    i -= ND4;
    if (i < H_ * HD_) g_bqs[i] = bq[i] * 0.125f * LOG2E;
}

// ---------------------------------------------------------------------------
// Transpose-convert Wq/Wk/Wv [h][d][e] -> g_wT [mat][h*64+e][k=d] fp16
// (Wq folds 0.125*log2e so QK logits are exp2-domain)
// ---------------------------------------------------------------------------
__global__ __launch_bounds__(256) void convertW_kernel(
    const float* __restrict__ Wq, const float* __restrict__ Wk,
    const float* __restrict__ Wv)
{
    __shared__ float t[64][65];
    const int dt = blockIdx.x, h = blockIdx.y, m = blockIdx.z;
    const float* W = (m == 0) ? Wq : (m == 1) ? Wk : Wv;
    const float sc = (m == 0) ? 0.125f * LOG2E : 1.f;
    const int tid = threadIdx.x;
    #pragma unroll
    for (int i = 0; i < 16; i++) {
        int g = i * 256 + tid;
        int dl = g >> 6, e = g & 63;
        t[dl][e] = W[((size_t)h * D_ + dt * 64 + dl) * HD_ + e];
    }
    __syncthreads();
    __half* dst = g_wT + (size_t)m * D_ * D_;
    #pragma unroll
    for (int i = 0; i < 16; i++) {
        int g = i * 256 + tid;
        int e = g >> 6, dl = g & 63;
        dst[((size_t)(h * 64 + e)) * D_ + dt * 64 + dl] = __float2half_rn(t[dl][e] * sc);
    }
}

// ---------------------------------------------------------------------------
// GEMM skeleton (fp16 mma.sync): CTA 128(M) x 256(N) x k-chunk 32.
// 8 warps (2x4), warp tile 64x64 -> 8 ldm4 : 32 HMMA per k16 step.
// 3-buffer cp.async ring (prefill 2, issue c+2 after barrier).
// A [row][k] and B [n][k] stride 40 halves; non-trans ldmatrix.
// ---------------------------------------------------------------------------
#define GA_ST 40
#define GAW   (128 * GA_ST)      // 5120 halves
#define GBW   (256 * GA_ST)      // 10240 halves
#define GSTG  (GAW + GBW)        // 15360 halves/stage
#define GEMM_SMEM (3 * GSTG * 2) // 92160 bytes

#define G_STAGE(c, s) {                                                        \
    uint32_t sb = sm0 + (s) * GSTG * 2;                                        \
    _Pragma("unroll")                                                          \
    for (int i = 0; i < 2; i++) {  /* A: 128x32 halves = 512 CP16 */           \
        int g = i * 256 + tid; int row = g >> 2; int kg = (g & 3) * 8;         \
        CP16(sb + (row * GA_ST + kg) * 2,                                      \
             Ap + (size_t)row * D_ + (c) * 32 + kg);                           \
    }                                                                          \
    _Pragma("unroll")                                                          \
    for (int i = 0; i < 4; i++) {  /* B: 256x32 halves = 1024 CP16 */          \
        int g = i * 256 + tid; int n = g >> 2; int kg = (g & 3) * 8;           \
        CP16(sb + (GAW + n * GA_ST + kg) * 2,                                  \
             Bp + (size_t)n * D_ + (c) * 32 + kg);                             \
    } }

#define G_BODY()                                                               \
    const int tid  = threadIdx.x;                                              \
    const int wid  = tid >> 5;                                                 \
    const int lane = tid & 31;                                                 \
    const int wm   = wid >> 2, wn = wid & 3;                                   \
    const int ql   = lane & 3, qr = lane >> 2;                                 \
    const uint32_t sm0 = smem_u32(gsm);                                        \
    const uint32_t aLane = ((wm * 64 + (lane & 15)) * GA_ST) * 2 + (lane >> 4) * 16; \
    const uint32_t bLane = ((wn * 64 + (lane & 15)) * GA_ST) * 2 + (lane >> 4) * 16; \
    float acc[4][8][4];                                                        \
    _Pragma("unroll")                                                          \
    for (int mi = 0; mi < 4; mi++)                                             \
        _Pragma("unroll")                                                      \
        for (int ni = 0; ni < 8; ni++)                                         \
            _Pragma("unroll")                                                  \
            for (int c = 0; c < 4; c++) acc[mi][ni][c] = 0.f;                  \
    G_STAGE(0, 0); CPCOMMIT();                                                 \
    G_STAGE(1, 1); CPCOMMIT();                                                 \
    for (int c = 0; c < 32; c++) {                                             \
        const int cur = c % 3;                                                 \
        CPWAIT(1);                                                             \
        __syncthreads();                                                       \
        if (c + 2 < 32) { G_STAGE(c + 2, (c + 2) % 3); }                       \
        CPCOMMIT();                                                            \
        const uint32_t sAb = sm0 + cur * GSTG * 2;                             \
        const uint32_t sBb = sAb + GAW * 2;                                    \
        _Pragma("unroll")                                                      \
        for (int kk = 0; kk < 2; kk++) {                                       \
            uint32_t a[4][4];                                                  \
            _Pragma("unroll")                                                  \
            for (int mi = 0; mi < 4; mi++)                                     \
                ldm4(a[mi], sAb + aLane + mi * 16 * GA_ST * 2 + kk * 32);      \
            uint32_t bb[4][4];                                                 \
            _Pragma("unroll")                                                  \
            for (int nj = 0; nj < 4; nj++)                                     \
                ldm4(bb[nj], sBb + bLane + nj * 16 * GA_ST * 2 + kk * 32);     \
            _Pragma("unroll")                                                  \
            for (int mi = 0; mi < 4; mi++)                                     \
                _Pragma("unroll")                                              \
                for (int nj = 0; nj < 4; nj++) {                               \
                    mma_f16(acc[mi][2 * nj],     a[mi], bb[nj][0], bb[nj][2]); \
                    mma_f16(acc[mi][2 * nj + 1], a[mi], bb[nj][1], bb[nj][3]); \
                }                                                              \
        }                                                                      \
    }

// ---------------------------------------------------------------------------
// QKV projection. grid (32 row-tiles, 4 col-tiles(=4 heads), 3 mats), 256 thr
// ---------------------------------------------------------------------------
__global__ __launch_bounds__(256) void qkv_gemm(
    const float* __restrict__ bk, const float* __restrict__ bv)
{
    extern __shared__ __align__(16) __half gsm[];
    const int rt = blockIdx.x, ct = blockIdx.y, m = blockIdx.z;
    const __half* Ap = g_xh + (size_t)(rt * 128) * D_;
    const __half* Bp = g_wT + ((size_t)m * D_ + ct * 256) * D_;
    const float* bias = (m == 0) ? g_bqs : (m == 1) ? bk : bv;
    __half* out = (m == 0) ? g_q : (m == 1) ? g_k : g_v;

    G_BODY();

    // epilogue: warp cols wn*64..+63 = exactly head h = ct*4 + wn
    const int h = ct * 4 + wn;
    #pragma unroll
    for (int mi = 0; mi < 4; mi++) {
        int row = rt * 128 + wm * 64 + mi * 16 + qr;
        int bb2 = row >> 11;
        int sg  = row & (S_ - 1);
        __half* o0 = out + (((size_t)bb2 * H_ + h) * S_ + sg) * HD_;
        __half* o1 = out + (((size_t)bb2 * H_ + h) * S_ + sg + 8) * HD_;
        #pragma unroll
        for (int ni = 0; ni < 8; ni++) {
            int e = ni * 8 + 2 * ql;
            float bv0 = bias[h * HD_ + e];
            float bv1 = bias[h * HD_ + e + 1];
            *(__half2*)(o0 + e) = __floats2half2_rn(acc[mi][ni][0] + bv0, acc[mi][ni][1] + bv1);
            *(__half2*)(o1 + e) = __floats2half2_rn(acc[mi][ni][2] + bv0, acc[mi][ni][3] + bv1);
        }
    }
}

// ---------------------------------------------------------------------------
// Output projection. grid (32, 4), 256 threads
// ---------------------------------------------------------------------------
__global__ __launch_bounds__(256) void oproj_gemm(
    const float* __restrict__ bo, float* __restrict__ out)
{
    extern __shared__ __align__(16) __half gsm[];
    const int rt = blockIdx.x, ct = blockIdx.y;
    const __half* Ap = g_wv + (size_t)(rt * 128) * D_;
    const __half* Bp = g_woh + (size_t)(ct * 256) * D_;

    G_BODY();

    #pragma unroll
    for (int mi = 0; mi < 4; mi++) {
        int row = rt * 128 + wm * 64 + mi * 16 + qr;
        #pragma unroll
        for (int ni = 0; ni < 8; ni++) {
            int col = ct * 256 + wn * 64 + ni * 8 + 2 * ql;
            float bv0 = bo[col], bv1 = bo[col + 1];
            *(float2*)&out[(size_t)row * D_ + col] =
                make_float2(acc[mi][ni][0] + bv0, acc[mi][ni][1] + bv1);
            *(float2*)&out[(size_t)(row + 8) * D_ + col] =
                make_float2(acc[mi][ni][2] + bv0, acc[mi][ni][3] + bv1);
        }
    }
}

// ---------------------------------------------------------------------------
// Flash attention (causal, fp16 mma.sync, exp2-domain softmax).
// 128 queries/block, 8 warps x 16 rows, double-buffered K/V, warp-local P.
// grid (16 reversed, 32), 256 threads, occupancy 2.
// ---------------------------------------------------------------------------
#define AT_ST 72
#define AK_W (64 * AT_ST)
#define AV_W (64 * AT_ST)
#define AP_OFF (2 * AK_W + 2 * AV_W)
#define AP_W  (128 * AT_ST)
#define ATT_SMEM ((AP_OFF + AP_W) * 2)  // 55296 bytes

__global__ __launch_bounds__(256, 2) void attn_kernel()
{
    extern __shared__ __half hsm[];
    __half* sP = hsm + AP_OFF;

    const int qt = 15 - blockIdx.x;
    const int bh = blockIdx.y;
    const int b  = bh >> 4;
    const int h  = bh & 15;
    const int tid  = threadIdx.x;
    const int w    = tid >> 5;
    const int lane = tid & 31;
    const int qr   = lane >> 2;
    const int ql   = lane & 3;

    const __half* Qb = g_q + (size_t)bh * S_ * HD_;
    const __half* Kb = g_k + (size_t)bh * S_ * HD_;
    const __half* Vb = g_v + (size_t)bh * S_ * HD_;

    const uint32_t sk_b = smem_u32(hsm);
    const uint32_t sv_b = sk_b + 2 * AK_W * 2;
    const uint32_t sp_b = sk_b + AP_OFF * 2;
    const uint32_t aoff = ((w * 16 + (lane & 15)) * AT_ST) * 2 + (lane >> 4) * 16;
    const uint32_t koff = ((lane & 15) * AT_ST) * 2 + (lane >> 4) * 16;
    const int klane = (lane & 7) + ((lane >> 3) & 1) * 8;
    const uint32_t voff = (klane * AT_ST + (lane >> 4) * 8) * 2;

    #pragma unroll
    for (int i = 0; i < 4; i++) {
        int g = i * 256 + tid;
        int row = g >> 3, kg = (g & 7) * 8;
        CP16(sp_b + (row * AT_ST + kg) * 2, &Qb[(size_t)(qt * 128 + row) * HD_ + kg]);
    }
    CPCOMMIT(); CPWAIT(0);
    __syncthreads();

    uint32_t qa[4][4];
    #pragma unroll
    for (int kk = 0; kk < 4; kk++) ldm4(qa[kk], sp_b + aoff + kk * 32);
    __syncthreads();

    #define ATT_STAGE(kt, s) {                                                 \
        _Pragma("unroll")                                                      \
        for (int i = 0; i < 4; i++) {                                          \
            int g = i * 256 + tid;                                             \
            int sel = g >> 9; int row = (g >> 3) & 63; int kg = (g & 7) * 8;   \
            uint32_t base = sel ? (sv_b + (s) * AV_W * 2) : (sk_b + (s) * AK_W * 2); \
            const __half* src = sel ? &Vb[(size_t)((kt) * 64 + row) * HD_ + kg] \
                                    : &Kb[(size_t)((kt) * 64 + row) * HD_ + kg]; \
            CP16(base + (row * AT_ST + kg) * 2, src);                          \
        }                                                                      \
    }

    ATT_STAGE(0, 0); CPCOMMIT();

    float O[8][4];
    #pragma unroll
    for (int n = 0; n < 8; n++)
        #pragma unroll
        for (int c = 0; c < 4; c++) O[n][c] = 0.f;
    float m0 = -1e30f, m1 = -1e30f, l0 = 0.f, l1 = 0.f;

    const int rbase = qt * 128 + w * 16;
    const int nkt = 2 * qt + 2;

    for (int kt = 0; kt < nkt; kt++) {
        const int buf = kt & 1;
        CPWAIT(0);
        __syncthreads();
        if (kt + 1 < nkt) { ATT_STAGE(kt + 1, buf ^ 1); }
        CPCOMMIT();

        if (kt * 64 > rbase + 15) continue;

        const uint32_t kbase = sk_b + buf * AK_W * 2;
        float sc[8][4];
        #pragma unroll
        for (int n = 0; n < 8; n++)
            #pragma unroll
            for (int c = 0; c < 4; c++) sc[n][c] = 0.f;
        #pragma unroll
        for (int kk = 0; kk < 4; kk++) {
            #pragma unroll
            for (int j = 0; j < 4; j++) {
                uint32_t kb[4];
                ldm4(kb, kbase + koff + j * 16 * AT_ST * 2 + kk * 32);
                mma_f16(sc[2 * j],     qa[kk], kb[0], kb[2]);
                mma_f16(sc[2 * j + 1], qa[kk], kb[1], kb[3]);
            }
        }

        if (kt * 64 + 63 > rbase) {
            const int r0 = rbase + qr;
            const int c0 = kt * 64;
            #pragma unroll
            for (int n = 0; n < 8; n++) {
                int cg = c0 + n * 8 + 2 * ql;
                if (cg     > r0)     sc[n][0] = -1e30f;
                if (cg + 1 > r0)     sc[n][1] = -1e30f;
                if (cg     > r0 + 8) sc[n][2] = -1e30f;
                if (cg + 1 > r0 + 8) sc[n][3] = -1e30f;
            }
        }

        float mt0 = -1e30f, mt1 = -1e30f;
        #pragma unroll
        for (int n = 0; n < 8; n++) {
            mt0 = fmaxf(mt0, fmaxf(sc[n][0], sc[n][1]));
            mt1 = fmaxf(mt1, fmaxf(sc[n][2], sc[n][3]));
        }
        mt0 = fmaxf(mt0, __shfl_xor_sync(0xffffffffu, mt0, 1));
        mt0 = fmaxf(mt0, __shfl_xor_sync(0xffffffffu, mt0, 2));
        mt1 = fmaxf(mt1, __shfl_xor_sync(0xffffffffu, mt1, 1));
        mt1 = fmaxf(mt1, __shfl_xor_sync(0xffffffffu, mt1, 2));
        float mn0 = fmaxf(m0, mt0), mn1 = fmaxf(m1, mt1);
        float cr0 = exp2f(m0 - mn0), cr1 = exp2f(m1 - mn1);
        m0 = mn0; m1 = mn1;
        #pragma unroll
        for (int n = 0; n < 8; n++) {
            O[n][0] *= cr0; O[n][1] *= cr0;
            O[n][2] *= cr1; O[n][3] *= cr1;
        }
        float s0 = 0.f, s1 = 0.f;
        #pragma unroll
        for (int n = 0; n < 8; n++) {
            sc[n][0] = exp2f(sc[n][0] - mn0);
            sc[n][1] = exp2f(sc[n][1] - mn0);
            sc[n][2] = exp2f(sc[n][2] - mn1);
            sc[n][3] = exp2f(sc[n][3] - mn1);
            s0 += sc[n][0] + sc[n][1];
            s1 += sc[n][2] + sc[n][3];
        }
        s0 += __shfl_xor_sync(0xffffffffu, s0, 1);
        s0 += __shfl_xor_sync(0xffffffffu, s0, 2);
        s1 += __shfl_xor_sync(0xffffffffu, s1, 1);
        s1 += __shfl_xor_sync(0xffffffffu, s1, 2);
        l0 = l0 * cr0 + s0;
        l1 = l1 * cr1 + s1;

        #pragma unroll
        for (int n = 0; n < 8; n++) {
            int cc = n * 8 + 2 * ql;
            *(__half2*)&sP[(w * 16 + qr) * AT_ST + cc] =
                __floats2half2_rn(sc[n][0], sc[n][1]);
            *(__half2*)&sP[(w * 16 + qr + 8) * AT_ST + cc] =
                __floats2half2_rn(sc[n][2], sc[n][3]);
        }
        __syncwarp();

        const uint32_t vbase = sv_b + buf * AV_W * 2;
        #pragma unroll
        for (int kk = 0; kk < 4; kk++) {
            uint32_t pa[4];
            ldm4(pa, sp_b + aoff + kk * 32);
            #pragma unroll
            for (int j = 0; j < 4; j++) {
                uint32_t vb[4];
                ldm4t(vb, vbase + voff + (kk * 16 * AT_ST + j * 16) * 2);
                mma_f16(O[2 * j],     pa, vb[0], vb[1]);
                mma_f16(O[2 * j + 1], pa, vb[2], vb[3]);
            }
        }
    }

    float inv0 = 1.f / l0, inv1 = 1.f / l1;
    int r0g = qt * 128 + w * 16 + qr;
    __half* base0 = g_wv + ((size_t)b * S_ + r0g) * D_ + h * HD_;
    __half* base1 = g_wv + ((size_t)b * S_ + r0g + 8) * D_ + h * HD_;
    #pragma unroll
    for (int n = 0; n < 8; n++) {
        int cc = n * 8 + 2 * ql;
        *(__half2*)&base0[cc] = __floats2half2_rn(O[n][0] * inv0, O[n][1] * inv0);
        *(__half2*)&base1[cc] = __floats2half2_rn(O[n][2] * inv1, O[n][3] * inv1);
    }
}

// ---------------------------------------------------------------------------
// Launch. metadata order: x, Wq, bq, Wk, bk, Wv, bv, Wo, bo
// ---------------------------------------------------------------------------
extern "C" void kernel_launch(void* const* d_in, const int* in_sizes, int n_in,
                              void* d_out, int out_size)
{
    const float* x  = (const float*)d_in[0];
    const float* Wq = (const float*)d_in[1];
    const float* bq = (const float*)d_in[2];
    const float* Wk = (const float*)d_in[3];
    const float* bk = (const float*)d_in[4];
    const float* Wv = (const float*)d_in[5];
    const float* bv = (const float*)d_in[6];
    const float* Wo = (const float*)d_in[7];
    const float* bo = (const float*)d_in[8];
    float* out = (float*)d_out;

    cudaFuncSetAttribute(qkv_gemm,    cudaFuncAttributeMaxDynamicSharedMemorySize, GEMM_SMEM);
    cudaFuncSetAttribute(oproj_gemm,  cudaFuncAttributeMaxDynamicSharedMemorySize, GEMM_SMEM);
    cudaFuncSetAttribute(attn_kernel, cudaFuncAttributeMaxDynamicSharedMemorySize, ATT_SMEM);

    const long long ntot = (long long)NX4 + ND4 + H_ * HD_;
    convert_kernel<<<(int)((ntot + 255) / 256), 256>>>(x, bq, Wo);
    convertW_kernel<<<dim3(16, 16, 3), 256>>>(Wq, Wk, Wv);

    qkv_gemm<<<dim3(32, 4, 3), 256, GEMM_SMEM>>>(bk, bv);

    attn_kernel<<<dim3(16, 32), 256, ATT_SMEM>>>();

    oproj_gemm<<<dim3(32, 4), 256, GEMM_SMEM>>>(bo, out);
}